// round 1
// baseline (speedup 1.0000x reference)
#include <cuda_runtime.h>
#include <math.h>

#define B_     2
#define L_     2048
#define HID_   4096
#define NHEAD_ 32
#define NKV_   8
#define HDIM_  128
#define MROWS  (B_*L_)          // 4096
#define KVW    (2*NKV_*HDIM_)   // 2048

// Scratch (allocation-free rule: __device__ globals)
__device__ __align__(256) float g_q  [(size_t)MROWS * HID_];   // Q proj   64 MB
__device__ __align__(256) float g_kv [(size_t)MROWS * KVW ];   // KV proj  32 MB
__device__ __align__(256) float g_att[(size_t)MROWS * HID_];   // attn out 64 MB

// ---------------------------------------------------------------------------
// SGEMM: C[M,N] = A[M,K] @ W[K,N] + bias[N]
// Block tile 128x128, K-tile 8, 256 threads, 8x8 per thread.
// Thread (tx,ty) owns rows by*128 + ty + 16*i, cols bx*128 + tx + 16*j
// (stride-16 ownership -> conflict-free smem reads, coalesced gmem stores).
// ---------------------------------------------------------------------------
__global__ __launch_bounds__(256) void sgemm_bias_k(
    const float* __restrict__ A, const float* __restrict__ W,
    const float* __restrict__ bias, float* __restrict__ C,
    int M, int N, int K)
{
    __shared__ float As[8][128];   // transposed: As[k][m]
    __shared__ float Ws[8][128];   // Ws[k][n]

    const int tid = threadIdx.x;
    const int tx = tid & 15, ty = tid >> 4;
    const int bx = blockIdx.x, by = blockIdx.y;

    float acc[8][8];
#pragma unroll
    for (int i = 0; i < 8; i++)
#pragma unroll
        for (int j = 0; j < 8; j++) acc[i][j] = 0.f;

    const int a_row = tid >> 1;          // 0..127
    const int a_col = (tid & 1) * 4;     // 0 or 4
    const int w_row = tid >> 5;          // 0..7
    const int w_col = (tid & 31) * 4;    // 0..124

    const float* Ap = A + (size_t)(by * 128 + a_row) * K + a_col;
    const float* Wp = W + (size_t)w_row * N + bx * 128 + w_col;

    for (int k0 = 0; k0 < K; k0 += 8) {
        float4 av = *(const float4*)(Ap + k0);
        As[a_col + 0][a_row] = av.x;
        As[a_col + 1][a_row] = av.y;
        As[a_col + 2][a_row] = av.z;
        As[a_col + 3][a_row] = av.w;
        float4 wv = *(const float4*)(Wp + (size_t)k0 * N);
        *(float4*)&Ws[w_row][w_col] = wv;
        __syncthreads();
#pragma unroll
        for (int kk = 0; kk < 8; ++kk) {
            float ar[8], wr[8];
#pragma unroll
            for (int i = 0; i < 8; i++) ar[i] = As[kk][ty + 16 * i];
#pragma unroll
            for (int j = 0; j < 8; j++) wr[j] = Ws[kk][tx + 16 * j];
#pragma unroll
            for (int i = 0; i < 8; i++)
#pragma unroll
                for (int j = 0; j < 8; j++)
                    acc[i][j] = fmaf(ar[i], wr[j], acc[i][j]);
        }
        __syncthreads();
    }

    float bv[8];
#pragma unroll
    for (int j = 0; j < 8; j++) bv[j] = bias[bx * 128 + tx + 16 * j];
#pragma unroll
    for (int i = 0; i < 8; i++) {
        float* Cp = C + (size_t)(by * 128 + ty + 16 * i) * N + bx * 128;
#pragma unroll
        for (int j = 0; j < 8; j++)
            Cp[tx + 16 * j] = acc[i][j] + bv[j];
    }
}

// ---------------------------------------------------------------------------
// Flash attention: one block = (batch b, head, 64-query tile).
// Streams K/V in 64-row tiles; online softmax; O accumulated in registers.
// Smem strides padded (132 / 66) to keep conflicts <= 2-way.
// ---------------------------------------------------------------------------
#define QS_STRIDE 132
#define SS_STRIDE 66
#define ATTN_SMEM_FLOATS (3*64*QS_STRIDE + 64*SS_STRIDE + 3*64)
#define ATTN_SMEM_BYTES  (ATTN_SMEM_FLOATS * 4)

__global__ __launch_bounds__(256) void attn_k()
{
    extern __shared__ float sm[];
    float* Qs   = sm;                    // 64 x 132
    float* Ks   = Qs + 64 * QS_STRIDE;   // 64 x 132
    float* Vs   = Ks + 64 * QS_STRIDE;   // 64 x 132
    float* Ss   = Vs + 64 * QS_STRIDE;   // 64 x 66
    float* m_s  = Ss + 64 * SS_STRIDE;   // 64
    float* l_s  = m_s + 64;              // 64
    float* fact = l_s + 64;              // 64

    const int b = blockIdx.z, head = blockIdx.y, qt = blockIdx.x;
    const int kvh = head >> 2;           // G = 4 query heads per KV head
    const int tid = threadIdx.x;
    const int tx = tid & 15, ty = tid >> 4;
    const float scale = 0.08838834764831845f;  // 1/sqrt(128)

    // Load Q tile (scaled)
    {
        const float* qbase = g_q + (size_t)(b * L_ + qt * 64) * HID_ + head * HDIM_;
        for (int idx = tid; idx < 64 * 32; idx += 256) {
            int r = idx >> 5, c4 = (idx & 31) << 2;
            float4 v = *(const float4*)(qbase + (size_t)r * HID_ + c4);
            float* q = Qs + r * QS_STRIDE + c4;
            q[0] = v.x * scale; q[1] = v.y * scale;
            q[2] = v.z * scale; q[3] = v.w * scale;
        }
    }
    if (tid < 64) { m_s[tid] = -3.0e38f; l_s[tid] = 0.f; }

    float o[4][8];
#pragma unroll
    for (int i = 0; i < 4; i++)
#pragma unroll
        for (int j = 0; j < 8; j++) o[i][j] = 0.f;

    __syncthreads();

    for (int t = 0; t < L_ / 64; ++t) {
        // Load K/V tiles (interleaved in g_kv: K at +0, V at +NKV*HDIM)
        {
            const float* kvbase = g_kv + (size_t)(b * L_ + t * 64) * KVW + kvh * HDIM_;
            for (int idx = tid; idx < 64 * 32; idx += 256) {
                int r = idx >> 5, c4 = (idx & 31) << 2;
                float4 kk4 = *(const float4*)(kvbase + (size_t)r * KVW + c4);
                *(float4*)(Ks + r * QS_STRIDE + c4) = kk4;
                float4 vv4 = *(const float4*)(kvbase + (size_t)r * KVW + NKV_ * HDIM_ + c4);
                *(float4*)(Vs + r * QS_STRIDE + c4) = vv4;
            }
        }
        __syncthreads();

        // S = Q K^T : thread owns rows ty*4+i, cols tx+16*j (j<4)
        float s[4][4];
#pragma unroll
        for (int i = 0; i < 4; i++)
#pragma unroll
            for (int j = 0; j < 4; j++) s[i][j] = 0.f;

        for (int d = 0; d < HDIM_; d += 4) {
            float4 q4[4], k4[4];
#pragma unroll
            for (int i = 0; i < 4; i++)
                q4[i] = *(const float4*)(Qs + (ty * 4 + i) * QS_STRIDE + d);
#pragma unroll
            for (int j = 0; j < 4; j++)
                k4[j] = *(const float4*)(Ks + (tx + 16 * j) * QS_STRIDE + d);
#pragma unroll
            for (int i = 0; i < 4; i++)
#pragma unroll
                for (int j = 0; j < 4; j++) {
                    s[i][j] = fmaf(q4[i].x, k4[j].x, s[i][j]);
                    s[i][j] = fmaf(q4[i].y, k4[j].y, s[i][j]);
                    s[i][j] = fmaf(q4[i].z, k4[j].z, s[i][j]);
                    s[i][j] = fmaf(q4[i].w, k4[j].w, s[i][j]);
                }
        }
#pragma unroll
        for (int i = 0; i < 4; i++)
#pragma unroll
            for (int j = 0; j < 4; j++)
                Ss[(ty * 4 + i) * SS_STRIDE + tx + 16 * j] = s[i][j];
        __syncthreads();

        // Online softmax update: 4 threads per row
        {
            const int r = tid >> 2, part = tid & 3;
            float* srow = Ss + r * SS_STRIDE;
            float rmax = -3.0e38f;
#pragma unroll
            for (int c = part * 16; c < part * 16 + 16; ++c)
                rmax = fmaxf(rmax, srow[c]);
            rmax = fmaxf(rmax, __shfl_xor_sync(0xffffffffu, rmax, 1));
            rmax = fmaxf(rmax, __shfl_xor_sync(0xffffffffu, rmax, 2));
            float mold = m_s[r];
            float mnew = fmaxf(mold, rmax);
            float sum = 0.f;
#pragma unroll
            for (int c = part * 16; c < part * 16 + 16; ++c) {
                float p = __expf(srow[c] - mnew);
                srow[c] = p;
                sum += p;
            }
            sum += __shfl_xor_sync(0xffffffffu, sum, 1);
            sum += __shfl_xor_sync(0xffffffffu, sum, 2);
            if (part == 0) {
                fact[r] = __expf(mold - mnew);
                m_s[r] = mnew;
                l_s[r] = l_s[r] * fact[r] + sum;
            }
        }
        __syncthreads();

        // O = O*fact + P @ V : thread owns rows ty*4+i, cols tx+16*j (j<8)
        float fr[4];
#pragma unroll
        for (int i = 0; i < 4; i++) fr[i] = fact[ty * 4 + i];
#pragma unroll
        for (int i = 0; i < 4; i++)
#pragma unroll
            for (int j = 0; j < 8; j++) o[i][j] *= fr[i];

#pragma unroll 2
        for (int kk = 0; kk < 64; ++kk) {
            float pv[4], vv[8];
#pragma unroll
            for (int i = 0; i < 4; i++) pv[i] = Ss[(ty * 4 + i) * SS_STRIDE + kk];
#pragma unroll
            for (int j = 0; j < 8; j++) vv[j] = Vs[kk * QS_STRIDE + tx + 16 * j];
#pragma unroll
            for (int i = 0; i < 4; i++)
#pragma unroll
                for (int j = 0; j < 8; j++)
                    o[i][j] = fmaf(pv[i], vv[j], o[i][j]);
        }
        __syncthreads();
    }

    // Normalize and store to g_att[b,l,head,hdim]
    float* obase = g_att + (size_t)(b * L_ + qt * 64) * HID_ + head * HDIM_;
#pragma unroll
    for (int i = 0; i < 4; i++) {
        float inv = 1.0f / l_s[ty * 4 + i];
        float* op = obase + (size_t)(ty * 4 + i) * HID_;
#pragma unroll
        for (int j = 0; j < 8; j++)
            op[tx + 16 * j] = o[i][j] * inv;
    }
}

// ---------------------------------------------------------------------------
extern "C" void kernel_launch(void* const* d_in, const int* in_sizes, int n_in,
                              void* d_out, int out_size)
{
    const float* query = (const float*)d_in[0];
    const float* kv    = (const float*)d_in[1];
    const float* Wq    = (const float*)d_in[2];
    const float* bq    = (const float*)d_in[3];
    const float* Wkv   = (const float*)d_in[4];
    const float* bkv   = (const float*)d_in[5];
    const float* Wo    = (const float*)d_in[6];
    const float* bo    = (const float*)d_in[7];
    float* out = (float*)d_out;

    float *pq = nullptr, *pkv = nullptr, *patt = nullptr;
    cudaGetSymbolAddress((void**)&pq,   g_q);
    cudaGetSymbolAddress((void**)&pkv,  g_kv);
    cudaGetSymbolAddress((void**)&patt, g_att);

    cudaFuncSetAttribute(attn_k, cudaFuncAttributeMaxDynamicSharedMemorySize,
                         ATTN_SMEM_BYTES);

    dim3 blk(256);
    // Q projection: [4096,4096] = query @ Wq + bq
    sgemm_bias_k<<<dim3(HID_ / 128, MROWS / 128), blk>>>(query, Wq, bq, pq,
                                                         MROWS, HID_, HID_);
    // KV projection: [4096,2048] = kv @ Wkv + bkv
    sgemm_bias_k<<<dim3(KVW / 128, MROWS / 128), blk>>>(kv, Wkv, bkv, pkv,
                                                        MROWS, KVW, HID_);
    // Grouped-KV flash attention
    attn_k<<<dim3(L_ / 64, NHEAD_, B_), blk, ATTN_SMEM_BYTES>>>();
    // Output projection: out = g_att @ Wo + bo
    sgemm_bias_k<<<dim3(HID_ / 128, MROWS / 128), blk>>>(patt, Wo, bo, out,
                                                         MROWS, HID_, HID_);
}

// round 3
// speedup vs baseline: 1.8082x; 1.8082x over previous
#include <cuda_runtime.h>
#include <cuda_bf16.h>
#include <cstdint>
#include <math.h>

#define B_     2
#define L_     2048
#define HID_   4096
#define NHEAD_ 32
#define NKV_   8
#define HDIM_  128
#define MROWS  (B_*L_)          // 4096
#define KVW    (2*NKV_*HDIM_)   // 2048

// ------------------------- device scratch (no allocs) -----------------------
__device__ __align__(256) float g_q  [(size_t)MROWS * HID_];
__device__ __align__(256) float g_kv [(size_t)MROWS * KVW ];
__device__ __align__(256) float g_att[(size_t)MROWS * HID_];

__device__ __align__(256) __nv_bfloat16 g_qin_h [(size_t)MROWS * HID_];
__device__ __align__(256) __nv_bfloat16 g_qin_l [(size_t)MROWS * HID_];
__device__ __align__(256) __nv_bfloat16 g_kvin_h[(size_t)MROWS * HID_];
__device__ __align__(256) __nv_bfloat16 g_kvin_l[(size_t)MROWS * HID_];
__device__ __align__(256) __nv_bfloat16 g_att_h [(size_t)MROWS * HID_];
__device__ __align__(256) __nv_bfloat16 g_att_l [(size_t)MROWS * HID_];
__device__ __align__(256) __nv_bfloat16 g_wqt_h [(size_t)HID_ * HID_];
__device__ __align__(256) __nv_bfloat16 g_wqt_l [(size_t)HID_ * HID_];
__device__ __align__(256) __nv_bfloat16 g_wkvt_h[(size_t)KVW  * HID_];
__device__ __align__(256) __nv_bfloat16 g_wkvt_l[(size_t)KVW  * HID_];
__device__ __align__(256) __nv_bfloat16 g_wot_h [(size_t)HID_ * HID_];
__device__ __align__(256) __nv_bfloat16 g_wot_l [(size_t)HID_ * HID_];

// ------------------------------ PTX helpers ---------------------------------
__device__ __forceinline__ uint32_t smem_u32(const void* p) {
    uint32_t a;
    asm("{ .reg .u64 t; cvta.to.shared.u64 t, %1; cvt.u32.u64 %0, t; }"
        : "=r"(a) : "l"(p));
    return a;
}

__device__ __forceinline__ void ldsm4(uint32_t* r, uint32_t addr) {
    asm volatile("ldmatrix.sync.aligned.m8n8.x4.shared.b16 {%0,%1,%2,%3}, [%4];"
                 : "=r"(r[0]), "=r"(r[1]), "=r"(r[2]), "=r"(r[3]) : "r"(addr));
}

__device__ __forceinline__ void mma16816(float* d, const uint32_t* a,
                                         const uint32_t* b) {
    asm volatile(
        "mma.sync.aligned.m16n8k16.row.col.f32.bf16.bf16.f32 "
        "{%0,%1,%2,%3}, {%4,%5,%6,%7}, {%8,%9}, {%0,%1,%2,%3};"
        : "+f"(d[0]), "+f"(d[1]), "+f"(d[2]), "+f"(d[3])
        : "r"(a[0]), "r"(a[1]), "r"(a[2]), "r"(a[3]), "r"(b[0]), "r"(b[1]));
}

// ---------------------------- conversion kernels ----------------------------
__global__ __launch_bounds__(256) void split_k(const float* __restrict__ in,
                                               __nv_bfloat16* __restrict__ hi,
                                               __nv_bfloat16* __restrict__ lo,
                                               int n4)
{
    int i = blockIdx.x * 256 + threadIdx.x;
    if (i >= n4) return;
    float4 v = ((const float4*)in)[i];
    __nv_bfloat16 h0 = __float2bfloat16(v.x), h1 = __float2bfloat16(v.y);
    __nv_bfloat16 h2 = __float2bfloat16(v.z), h3 = __float2bfloat16(v.w);
    __nv_bfloat16 l0 = __float2bfloat16(v.x - __bfloat162float(h0));
    __nv_bfloat16 l1 = __float2bfloat16(v.y - __bfloat162float(h1));
    __nv_bfloat16 l2 = __float2bfloat16(v.z - __bfloat162float(h2));
    __nv_bfloat16 l3 = __float2bfloat16(v.w - __bfloat162float(h3));
    ushort4 hv, lv;
    hv.x = *(unsigned short*)&h0; hv.y = *(unsigned short*)&h1;
    hv.z = *(unsigned short*)&h2; hv.w = *(unsigned short*)&h3;
    lv.x = *(unsigned short*)&l0; lv.y = *(unsigned short*)&l1;
    lv.z = *(unsigned short*)&l2; lv.w = *(unsigned short*)&l3;
    ((ushort4*)hi)[i] = hv;
    ((ushort4*)lo)[i] = lv;
}

// W[K][N] fp32 -> Wt_hi/lo[N][K] bf16 (tiled transpose)
__global__ __launch_bounds__(256) void tsplit_k(const float* __restrict__ W,
                                                __nv_bfloat16* __restrict__ Th,
                                                __nv_bfloat16* __restrict__ Tl,
                                                int K, int N)
{
    __shared__ float t[32][33];
    int tx = threadIdx.x, ty = threadIdx.y;   // 32 x 8
    int n0 = blockIdx.x * 32, k0 = blockIdx.y * 32;
#pragma unroll
    for (int i = 0; i < 4; i++)
        t[ty + 8 * i][tx] = W[(size_t)(k0 + ty + 8 * i) * N + n0 + tx];
    __syncthreads();
#pragma unroll
    for (int i = 0; i < 4; i++) {
        float v = t[tx][ty + 8 * i];
        __nv_bfloat16 h = __float2bfloat16(v);
        __nv_bfloat16 l = __float2bfloat16(v - __bfloat162float(h));
        size_t o = (size_t)(n0 + ty + 8 * i) * K + k0 + tx;
        Th[o] = h; Tl[o] = l;
    }
}

// ---------------------------- HMMA GEMM -------------------------------------
// C[M,N] = A[M,K] @ Bt[N,K]^T + bias, via mma.sync m16n8k16 bf16, hi/lo split.
// CTA tile 128x128, K-tile 32, 256 threads (8 warps, 64x32 warp tiles).
// Smem row stride 40 bf16 (80B) -> conflict-free ldmatrix.
#define SSTRIDE 40

__global__ __launch_bounds__(256) void hgemm_k(
    const __nv_bfloat16* __restrict__ Ah, const __nv_bfloat16* __restrict__ Al,
    const __nv_bfloat16* __restrict__ Bh, const __nv_bfloat16* __restrict__ Bl,
    const float* __restrict__ bias, float* __restrict__ C,
    int M, int N, int K)
{
    __shared__ __nv_bfloat16 sAh[128 * SSTRIDE], sAl[128 * SSTRIDE];
    __shared__ __nv_bfloat16 sBh[128 * SSTRIDE], sBl[128 * SSTRIDE];

    const int tid  = threadIdx.x;
    const int wid  = tid >> 5, lane = tid & 31;
    const int gr   = lane >> 2, tg = lane & 3;
    const int wm   = (wid & 1) * 64;       // warp M origin in tile
    const int wn   = (wid >> 1) * 32;      // warp N origin in tile
    const int row0 = blockIdx.y * 128, col0 = blockIdx.x * 128;
    const int q    = lane >> 3, rr = lane & 7;

    float acc[4][4][4];
#pragma unroll
    for (int mt = 0; mt < 4; mt++)
#pragma unroll
        for (int nt = 0; nt < 4; nt++)
#pragma unroll
            for (int e = 0; e < 4; e++) acc[mt][nt][e] = 0.f;

    const uint32_t aAh = smem_u32(sAh), aAl = smem_u32(sAl);
    const uint32_t aBh = smem_u32(sBh), aBl = smem_u32(sBl);

    // gmem load mapping: 512 uint4 per tile (128 rows x 4 chunks), 2 per thread
    const int lr0 = tid >> 2, lc0 = (tid & 3) * 8;       // i=0
    const int lr1 = (tid + 256) >> 2;                     // i=1 (same lc)
    const __nv_bfloat16* pAh = Ah + (size_t)row0 * K;
    const __nv_bfloat16* pAl = Al + (size_t)row0 * K;
    const __nv_bfloat16* pBh = Bh + (size_t)col0 * K;
    const __nv_bfloat16* pBl = Bl + (size_t)col0 * K;

    for (int kt = 0; kt < K; kt += 32) {
        // stage 4 tiles (A hi/lo, B hi/lo), 128x32 bf16 each
        *(uint4*)&sAh[lr0 * SSTRIDE + lc0] = *(const uint4*)(pAh + (size_t)lr0 * K + kt + lc0);
        *(uint4*)&sAh[lr1 * SSTRIDE + lc0] = *(const uint4*)(pAh + (size_t)lr1 * K + kt + lc0);
        *(uint4*)&sAl[lr0 * SSTRIDE + lc0] = *(const uint4*)(pAl + (size_t)lr0 * K + kt + lc0);
        *(uint4*)&sAl[lr1 * SSTRIDE + lc0] = *(const uint4*)(pAl + (size_t)lr1 * K + kt + lc0);
        *(uint4*)&sBh[lr0 * SSTRIDE + lc0] = *(const uint4*)(pBh + (size_t)lr0 * K + kt + lc0);
        *(uint4*)&sBh[lr1 * SSTRIDE + lc0] = *(const uint4*)(pBh + (size_t)lr1 * K + kt + lc0);
        *(uint4*)&sBl[lr0 * SSTRIDE + lc0] = *(const uint4*)(pBl + (size_t)lr0 * K + kt + lc0);
        *(uint4*)&sBl[lr1 * SSTRIDE + lc0] = *(const uint4*)(pBl + (size_t)lr1 * K + kt + lc0);
        __syncthreads();

#pragma unroll
        for (int ks = 0; ks < 2; ++ks) {
            uint32_t fAh[4][4], fAl[4][4], fBh[2][4], fBl[2][4];
#pragma unroll
            for (int mt = 0; mt < 4; ++mt) {
                uint32_t off = (uint32_t)((wm + mt * 16 + (q & 1) * 8 + rr) * (SSTRIDE * 2)
                                          + (ks * 16 + (q >> 1) * 8) * 2);
                ldsm4(fAh[mt], aAh + off);
                ldsm4(fAl[mt], aAl + off);
            }
#pragma unroll
            for (int np = 0; np < 2; ++np) {
                uint32_t off = (uint32_t)((wn + np * 16 + (q >> 1) * 8 + rr) * (SSTRIDE * 2)
                                          + (ks * 16 + (q & 1) * 8) * 2);
                ldsm4(fBh[np], aBh + off);
                ldsm4(fBl[np], aBl + off);
            }
#pragma unroll
            for (int mt = 0; mt < 4; ++mt)
#pragma unroll
                for (int nt = 0; nt < 4; ++nt) {
                    const uint32_t* bh = &fBh[nt >> 1][(nt & 1) * 2];
                    const uint32_t* bl = &fBl[nt >> 1][(nt & 1) * 2];
                    mma16816(acc[mt][nt], fAh[mt], bh);
                    mma16816(acc[mt][nt], fAl[mt], bh);
                    mma16816(acc[mt][nt], fAh[mt], bl);
                }
        }
        __syncthreads();
    }

    // epilogue: direct float2 stores + bias
#pragma unroll
    for (int mt = 0; mt < 4; ++mt) {
#pragma unroll
        for (int nt = 0; nt < 4; ++nt) {
            int r = row0 + wm + mt * 16 + gr;
            int c = col0 + wn + nt * 8 + tg * 2;
            float b0 = bias[c], b1 = bias[c + 1];
            float2 v0 = make_float2(acc[mt][nt][0] + b0, acc[mt][nt][1] + b1);
            float2 v1 = make_float2(acc[mt][nt][2] + b0, acc[mt][nt][3] + b1);
            *(float2*)(C + (size_t)r * N + c) = v0;
            *(float2*)(C + (size_t)(r + 8) * N + c) = v1;
        }
    }
}

// ---------------------------------------------------------------------------
// Flash attention (fp32) — unchanged from round 1 (validated)
// ---------------------------------------------------------------------------
#define QS_STRIDE 132
#define SS_STRIDE 66
#define ATTN_SMEM_FLOATS (3*64*QS_STRIDE + 64*SS_STRIDE + 3*64)
#define ATTN_SMEM_BYTES  (ATTN_SMEM_FLOATS * 4)

__global__ __launch_bounds__(256) void attn_k()
{
    extern __shared__ float sm[];
    float* Qs   = sm;
    float* Ks   = Qs + 64 * QS_STRIDE;
    float* Vs   = Ks + 64 * QS_STRIDE;
    float* Ss   = Vs + 64 * QS_STRIDE;
    float* m_s  = Ss + 64 * SS_STRIDE;
    float* l_s  = m_s + 64;
    float* fact = l_s + 64;

    const int b = blockIdx.z, head = blockIdx.y, qt = blockIdx.x;
    const int kvh = head >> 2;
    const int tid = threadIdx.x;
    const int tx = tid & 15, ty = tid >> 4;
    const float scale = 0.08838834764831845f;

    {
        const float* qbase = g_q + (size_t)(b * L_ + qt * 64) * HID_ + head * HDIM_;
        for (int idx = tid; idx < 64 * 32; idx += 256) {
            int r = idx >> 5, c4 = (idx & 31) << 2;
            float4 v = *(const float4*)(qbase + (size_t)r * HID_ + c4);
            float* qp = Qs + r * QS_STRIDE + c4;
            qp[0] = v.x * scale; qp[1] = v.y * scale;
            qp[2] = v.z * scale; qp[3] = v.w * scale;
        }
    }
    if (tid < 64) { m_s[tid] = -3.0e38f; l_s[tid] = 0.f; }

    float o[4][8];
#pragma unroll
    for (int i = 0; i < 4; i++)
#pragma unroll
        for (int j = 0; j < 8; j++) o[i][j] = 0.f;

    __syncthreads();

    for (int t = 0; t < L_ / 64; ++t) {
        {
            const float* kvbase = g_kv + (size_t)(b * L_ + t * 64) * KVW + kvh * HDIM_;
            for (int idx = tid; idx < 64 * 32; idx += 256) {
                int r = idx >> 5, c4 = (idx & 31) << 2;
                float4 kk4 = *(const float4*)(kvbase + (size_t)r * KVW + c4);
                *(float4*)(Ks + r * QS_STRIDE + c4) = kk4;
                float4 vv4 = *(const float4*)(kvbase + (size_t)r * KVW + NKV_ * HDIM_ + c4);
                *(float4*)(Vs + r * QS_STRIDE + c4) = vv4;
            }
        }
        __syncthreads();

        float s[4][4];
#pragma unroll
        for (int i = 0; i < 4; i++)
#pragma unroll
            for (int j = 0; j < 4; j++) s[i][j] = 0.f;

        for (int d = 0; d < HDIM_; d += 4) {
            float4 q4[4], k4[4];
#pragma unroll
            for (int i = 0; i < 4; i++)
                q4[i] = *(const float4*)(Qs + (ty * 4 + i) * QS_STRIDE + d);
#pragma unroll
            for (int j = 0; j < 4; j++)
                k4[j] = *(const float4*)(Ks + (tx + 16 * j) * QS_STRIDE + d);
#pragma unroll
            for (int i = 0; i < 4; i++)
#pragma unroll
                for (int j = 0; j < 4; j++) {
                    s[i][j] = fmaf(q4[i].x, k4[j].x, s[i][j]);
                    s[i][j] = fmaf(q4[i].y, k4[j].y, s[i][j]);
                    s[i][j] = fmaf(q4[i].z, k4[j].z, s[i][j]);
                    s[i][j] = fmaf(q4[i].w, k4[j].w, s[i][j]);
                }
        }
#pragma unroll
        for (int i = 0; i < 4; i++)
#pragma unroll
            for (int j = 0; j < 4; j++)
                Ss[(ty * 4 + i) * SS_STRIDE + tx + 16 * j] = s[i][j];
        __syncthreads();

        {
            const int r = tid >> 2, part = tid & 3;
            float* srow = Ss + r * SS_STRIDE;
            float rmax = -3.0e38f;
#pragma unroll
            for (int c = part * 16; c < part * 16 + 16; ++c)
                rmax = fmaxf(rmax, srow[c]);
            rmax = fmaxf(rmax, __shfl_xor_sync(0xffffffffu, rmax, 1));
            rmax = fmaxf(rmax, __shfl_xor_sync(0xffffffffu, rmax, 2));
            float mold = m_s[r];
            float mnew = fmaxf(mold, rmax);
            float sum = 0.f;
#pragma unroll
            for (int c = part * 16; c < part * 16 + 16; ++c) {
                float p = __expf(srow[c] - mnew);
                srow[c] = p;
                sum += p;
            }
            sum += __shfl_xor_sync(0xffffffffu, sum, 1);
            sum += __shfl_xor_sync(0xffffffffu, sum, 2);
            if (part == 0) {
                fact[r] = __expf(mold - mnew);
                m_s[r] = mnew;
                l_s[r] = l_s[r] * fact[r] + sum;
            }
        }
        __syncthreads();

        float fr[4];
#pragma unroll
        for (int i = 0; i < 4; i++) fr[i] = fact[ty * 4 + i];
#pragma unroll
        for (int i = 0; i < 4; i++)
#pragma unroll
            for (int j = 0; j < 8; j++) o[i][j] *= fr[i];

#pragma unroll 2
        for (int kk = 0; kk < 64; ++kk) {
            float pv[4], vv[8];
#pragma unroll
            for (int i = 0; i < 4; i++) pv[i] = Ss[(ty * 4 + i) * SS_STRIDE + kk];
#pragma unroll
            for (int j = 0; j < 8; j++) vv[j] = Vs[kk * QS_STRIDE + tx + 16 * j];
#pragma unroll
            for (int i = 0; i < 4; i++)
#pragma unroll
                for (int j = 0; j < 8; j++)
                    o[i][j] = fmaf(pv[i], vv[j], o[i][j]);
        }
        __syncthreads();
    }

    float* obase = g_att + (size_t)(b * L_ + qt * 64) * HID_ + head * HDIM_;
#pragma unroll
    for (int i = 0; i < 4; i++) {
        float inv = 1.0f / l_s[ty * 4 + i];
        float* op = obase + (size_t)(ty * 4 + i) * HID_;
#pragma unroll
        for (int j = 0; j < 8; j++)
            op[tx + 16 * j] = o[i][j] * inv;
    }
}

// ---------------------------------------------------------------------------
extern "C" void kernel_launch(void* const* d_in, const int* in_sizes, int n_in,
                              void* d_out, int out_size)
{
    const float* query = (const float*)d_in[0];
    const float* kv    = (const float*)d_in[1];
    const float* Wq    = (const float*)d_in[2];
    const float* bq    = (const float*)d_in[3];
    const float* Wkv   = (const float*)d_in[4];
    const float* bkv   = (const float*)d_in[5];
    const float* Wo    = (const float*)d_in[6];
    const float* bo    = (const float*)d_in[7];
    float* out = (float*)d_out;

    float *pq = nullptr, *pkv = nullptr, *patt = nullptr;
    cudaGetSymbolAddress((void**)&pq,   g_q);
    cudaGetSymbolAddress((void**)&pkv,  g_kv);
    cudaGetSymbolAddress((void**)&patt, g_att);
    __nv_bfloat16 *qh, *ql, *kvh, *kvl, *ath, *atl;
    __nv_bfloat16 *wqh, *wql, *wkh, *wkl, *woh, *wol;
    cudaGetSymbolAddress((void**)&qh,  g_qin_h);  cudaGetSymbolAddress((void**)&ql,  g_qin_l);
    cudaGetSymbolAddress((void**)&kvh, g_kvin_h); cudaGetSymbolAddress((void**)&kvl, g_kvin_l);
    cudaGetSymbolAddress((void**)&ath, g_att_h);  cudaGetSymbolAddress((void**)&atl, g_att_l);
    cudaGetSymbolAddress((void**)&wqh, g_wqt_h);  cudaGetSymbolAddress((void**)&wql, g_wqt_l);
    cudaGetSymbolAddress((void**)&wkh, g_wkvt_h); cudaGetSymbolAddress((void**)&wkl, g_wkvt_l);
    cudaGetSymbolAddress((void**)&woh, g_wot_h);  cudaGetSymbolAddress((void**)&wol, g_wot_l);

    cudaFuncSetAttribute(attn_k, cudaFuncAttributeMaxDynamicSharedMemorySize,
                         ATTN_SMEM_BYTES);

    const int n_act4 = (MROWS * HID_) / 4;
    // 1) split activations into bf16 hi/lo
    split_k<<<(n_act4 + 255) / 256, 256>>>(query, qh, ql, n_act4);
    split_k<<<(n_act4 + 255) / 256, 256>>>(kv, kvh, kvl, n_act4);
    // 2) transpose+split weights
    tsplit_k<<<dim3(HID_ / 32, HID_ / 32), dim3(32, 8)>>>(Wq,  wqh, wql, HID_, HID_);
    tsplit_k<<<dim3(KVW  / 32, HID_ / 32), dim3(32, 8)>>>(Wkv, wkh, wkl, HID_, KVW);
    tsplit_k<<<dim3(HID_ / 32, HID_ / 32), dim3(32, 8)>>>(Wo,  woh, wol, HID_, HID_);
    // 3) projections on tensor cores (HMMA)
    hgemm_k<<<dim3(HID_ / 128, MROWS / 128), 256>>>(qh, ql, wqh, wql, bq, pq,
                                                    MROWS, HID_, HID_);
    hgemm_k<<<dim3(KVW / 128, MROWS / 128), 256>>>(kvh, kvl, wkh, wkl, bkv, pkv,
                                                   MROWS, KVW, HID_);
    // 4) attention (fp32)
    attn_k<<<dim3(L_ / 64, NHEAD_, B_), 256, ATTN_SMEM_BYTES>>>();
    // 5) split attention output, O-projection
    split_k<<<(n_act4 + 255) / 256, 256>>>(patt, ath, atl, n_act4);
    hgemm_k<<<dim3(HID_ / 128, MROWS / 128), 256>>>(ath, atl, woh, wol, bo, out,
                                                    MROWS, HID_, HID_);
}

// round 4
// speedup vs baseline: 3.5167x; 1.9449x over previous
#include <cuda_runtime.h>
#include <cuda_bf16.h>
#include <cstdint>
#include <math.h>

#define B_     2
#define L_     2048
#define HID_   4096
#define NHEAD_ 32
#define NKV_   8
#define HDIM_  128
#define MROWS  (B_*L_)          // 4096
#define KVW    (2*NKV_*HDIM_)   // 2048

// ------------------------- device scratch (no allocs) -----------------------
__device__ __align__(256) float g_q  [(size_t)MROWS * HID_];
__device__ __align__(256) float g_kv [(size_t)MROWS * KVW ];

__device__ __align__(256) __nv_bfloat16 g_qin_h [(size_t)MROWS * HID_];
__device__ __align__(256) __nv_bfloat16 g_qin_l [(size_t)MROWS * HID_];
__device__ __align__(256) __nv_bfloat16 g_kvin_h[(size_t)MROWS * HID_];
__device__ __align__(256) __nv_bfloat16 g_kvin_l[(size_t)MROWS * HID_];
__device__ __align__(256) __nv_bfloat16 g_att_h [(size_t)MROWS * HID_];
__device__ __align__(256) __nv_bfloat16 g_att_l [(size_t)MROWS * HID_];
__device__ __align__(256) __nv_bfloat16 g_wqt_h [(size_t)HID_ * HID_];
__device__ __align__(256) __nv_bfloat16 g_wqt_l [(size_t)HID_ * HID_];
__device__ __align__(256) __nv_bfloat16 g_wkvt_h[(size_t)KVW  * HID_];
__device__ __align__(256) __nv_bfloat16 g_wkvt_l[(size_t)KVW  * HID_];
__device__ __align__(256) __nv_bfloat16 g_wot_h [(size_t)HID_ * HID_];
__device__ __align__(256) __nv_bfloat16 g_wot_l [(size_t)HID_ * HID_];
// attention operands (bf16 hi/lo)
__device__ __align__(256) __nv_bfloat16 g_aqh[(size_t)MROWS * HID_];  // scaled Q
__device__ __align__(256) __nv_bfloat16 g_aql[(size_t)MROWS * HID_];
__device__ __align__(256) __nv_bfloat16 g_kh [(size_t)B_*NKV_*L_*HDIM_]; // [b,kvh,l,d]
__device__ __align__(256) __nv_bfloat16 g_kl [(size_t)B_*NKV_*L_*HDIM_];
__device__ __align__(256) __nv_bfloat16 g_vth[(size_t)B_*NKV_*HDIM_*L_]; // [b,kvh,d,l]
__device__ __align__(256) __nv_bfloat16 g_vtl[(size_t)B_*NKV_*HDIM_*L_];

// ------------------------------ PTX helpers ---------------------------------
__device__ __forceinline__ uint32_t smem_u32(const void* p) {
    uint32_t a;
    asm("{ .reg .u64 t; cvta.to.shared.u64 t, %1; cvt.u32.u64 %0, t; }"
        : "=r"(a) : "l"(p));
    return a;
}

__device__ __forceinline__ void ldsm4(uint32_t* r, uint32_t addr) {
    asm volatile("ldmatrix.sync.aligned.m8n8.x4.shared.b16 {%0,%1,%2,%3}, [%4];"
                 : "=r"(r[0]), "=r"(r[1]), "=r"(r[2]), "=r"(r[3]) : "r"(addr));
}

__device__ __forceinline__ void mma16816(float* d, const uint32_t* a,
                                         const uint32_t* b) {
    asm volatile(
        "mma.sync.aligned.m16n8k16.row.col.f32.bf16.bf16.f32 "
        "{%0,%1,%2,%3}, {%4,%5,%6,%7}, {%8,%9}, {%0,%1,%2,%3};"
        : "+f"(d[0]), "+f"(d[1]), "+f"(d[2]), "+f"(d[3])
        : "r"(a[0]), "r"(a[1]), "r"(a[2]), "r"(a[3]), "r"(b[0]), "r"(b[1]));
}

__device__ __forceinline__ unsigned short f2bf_bits(float x) {
    __nv_bfloat16 h = __float2bfloat16(x);
    return *(unsigned short*)&h;
}
__device__ __forceinline__ float bf_bits2f(unsigned short b) {
    __nv_bfloat16 h = *(__nv_bfloat16*)&b;
    return __bfloat162float(h);
}

// ---------------------------- conversion kernels ----------------------------
__global__ __launch_bounds__(256) void split_k(const float* __restrict__ in,
                                               __nv_bfloat16* __restrict__ hi,
                                               __nv_bfloat16* __restrict__ lo,
                                               int n4, float scale)
{
    int i = blockIdx.x * 256 + threadIdx.x;
    if (i >= n4) return;
    float4 v = ((const float4*)in)[i];
    v.x *= scale; v.y *= scale; v.z *= scale; v.w *= scale;
    unsigned short h0 = f2bf_bits(v.x), h1 = f2bf_bits(v.y);
    unsigned short h2 = f2bf_bits(v.z), h3 = f2bf_bits(v.w);
    unsigned short l0 = f2bf_bits(v.x - bf_bits2f(h0));
    unsigned short l1 = f2bf_bits(v.y - bf_bits2f(h1));
    unsigned short l2 = f2bf_bits(v.z - bf_bits2f(h2));
    unsigned short l3 = f2bf_bits(v.w - bf_bits2f(h3));
    ((ushort4*)hi)[i] = make_ushort4(h0, h1, h2, h3);
    ((ushort4*)lo)[i] = make_ushort4(l0, l1, l2, l3);
}

// W[K][N] fp32 -> Wt_hi/lo[N][K] bf16 (tiled transpose)
__global__ __launch_bounds__(256) void tsplit_k(const float* __restrict__ W,
                                                __nv_bfloat16* __restrict__ Th,
                                                __nv_bfloat16* __restrict__ Tl,
                                                int K, int N)
{
    __shared__ float t[32][33];
    int tx = threadIdx.x, ty = threadIdx.y;   // 32 x 8
    int n0 = blockIdx.x * 32, k0 = blockIdx.y * 32;
#pragma unroll
    for (int i = 0; i < 4; i++)
        t[ty + 8 * i][tx] = W[(size_t)(k0 + ty + 8 * i) * N + n0 + tx];
    __syncthreads();
#pragma unroll
    for (int i = 0; i < 4; i++) {
        float v = t[tx][ty + 8 * i];
        unsigned short h = f2bf_bits(v);
        unsigned short l = f2bf_bits(v - bf_bits2f(h));
        size_t o = (size_t)(n0 + ty + 8 * i) * K + k0 + tx;
        Th[o] = *(__nv_bfloat16*)&h; Tl[o] = *(__nv_bfloat16*)&l;
    }
}

// K prep: g_kv fp32 [b*L+l][kvh*128+d] -> kh/kl [b,kvh,l,d] bf16
__global__ __launch_bounds__(256) void kprep_k(const float* __restrict__ KV,
                                               __nv_bfloat16* __restrict__ Kh,
                                               __nv_bfloat16* __restrict__ Kl)
{
    int i = blockIdx.x * 256 + threadIdx.x;           // over 4-elem chunks
    const int total = B_ * NKV_ * L_ * (HDIM_ / 4);
    if (i >= total) return;
    int c   = i & 31;                  // 32 chunks per row
    int l   = (i >> 5) & (L_ - 1);
    int kvh = (i >> 16) & 7;           // 32*2048 = 65536
    int b   = i >> 19;
    float4 v = *(const float4*)(KV + (size_t)(b * L_ + l) * KVW + kvh * HDIM_ + c * 4);
    unsigned short h0 = f2bf_bits(v.x), h1 = f2bf_bits(v.y);
    unsigned short h2 = f2bf_bits(v.z), h3 = f2bf_bits(v.w);
    unsigned short l0 = f2bf_bits(v.x - bf_bits2f(h0));
    unsigned short l1 = f2bf_bits(v.y - bf_bits2f(h1));
    unsigned short l2 = f2bf_bits(v.z - bf_bits2f(h2));
    unsigned short l3 = f2bf_bits(v.w - bf_bits2f(h3));
    size_t o = ((size_t)((b * NKV_ + kvh) * L_ + l) * HDIM_ + c * 4) / 4;
    ((ushort4*)Kh)[o] = make_ushort4(h0, h1, h2, h3);
    ((ushort4*)Kl)[o] = make_ushort4(l0, l1, l2, l3);
}

// V prep: g_kv fp32 V section -> vth/vtl [b,kvh,d,l] bf16 (transpose)
__global__ __launch_bounds__(256) void vtprep_k(const float* __restrict__ KV,
                                                __nv_bfloat16* __restrict__ Vh,
                                                __nv_bfloat16* __restrict__ Vl)
{
    __shared__ float t[32][33];
    int tx = threadIdx.x, ty = threadIdx.y;   // 32 x 8
    int l0 = blockIdx.x * 32, d0 = blockIdx.y * 32;
    int bk = blockIdx.z;                      // b*8 + kvh
    int b = bk >> 3, kvh = bk & 7;
#pragma unroll
    for (int i = 0; i < 4; i++)
        t[ty + 8 * i][tx] = KV[(size_t)(b * L_ + l0 + ty + 8 * i) * KVW
                               + NKV_ * HDIM_ + kvh * HDIM_ + d0 + tx];
    __syncthreads();
#pragma unroll
    for (int i = 0; i < 4; i++) {
        float v = t[tx][ty + 8 * i];
        unsigned short h = f2bf_bits(v);
        unsigned short l = f2bf_bits(v - bf_bits2f(h));
        size_t o = ((size_t)bk * HDIM_ + d0 + ty + 8 * i) * L_ + l0 + tx;
        Vh[o] = *(__nv_bfloat16*)&h; Vl[o] = *(__nv_bfloat16*)&l;
    }
}

// ---------------------------- HMMA GEMM (validated R3) ----------------------
#define SSTRIDE 40

__global__ __launch_bounds__(256) void hgemm_k(
    const __nv_bfloat16* __restrict__ Ah, const __nv_bfloat16* __restrict__ Al,
    const __nv_bfloat16* __restrict__ Bh, const __nv_bfloat16* __restrict__ Bl,
    const float* __restrict__ bias, float* __restrict__ C,
    int M, int N, int K)
{
    __shared__ __nv_bfloat16 sAh[128 * SSTRIDE], sAl[128 * SSTRIDE];
    __shared__ __nv_bfloat16 sBh[128 * SSTRIDE], sBl[128 * SSTRIDE];

    const int tid  = threadIdx.x;
    const int wid  = tid >> 5, lane = tid & 31;
    const int gr   = lane >> 2, tg = lane & 3;
    const int wm   = (wid & 1) * 64;
    const int wn   = (wid >> 1) * 32;
    const int row0 = blockIdx.y * 128, col0 = blockIdx.x * 128;
    const int q    = lane >> 3, rr = lane & 7;

    float acc[4][4][4];
#pragma unroll
    for (int mt = 0; mt < 4; mt++)
#pragma unroll
        for (int nt = 0; nt < 4; nt++)
#pragma unroll
            for (int e = 0; e < 4; e++) acc[mt][nt][e] = 0.f;

    const uint32_t aAh = smem_u32(sAh), aAl = smem_u32(sAl);
    const uint32_t aBh = smem_u32(sBh), aBl = smem_u32(sBl);

    const int lr0 = tid >> 2, lc0 = (tid & 3) * 8;
    const int lr1 = (tid + 256) >> 2;
    const __nv_bfloat16* pAh = Ah + (size_t)row0 * K;
    const __nv_bfloat16* pAl = Al + (size_t)row0 * K;
    const __nv_bfloat16* pBh = Bh + (size_t)col0 * K;
    const __nv_bfloat16* pBl = Bl + (size_t)col0 * K;

    for (int kt = 0; kt < K; kt += 32) {
        *(uint4*)&sAh[lr0 * SSTRIDE + lc0] = *(const uint4*)(pAh + (size_t)lr0 * K + kt + lc0);
        *(uint4*)&sAh[lr1 * SSTRIDE + lc0] = *(const uint4*)(pAh + (size_t)lr1 * K + kt + lc0);
        *(uint4*)&sAl[lr0 * SSTRIDE + lc0] = *(const uint4*)(pAl + (size_t)lr0 * K + kt + lc0);
        *(uint4*)&sAl[lr1 * SSTRIDE + lc0] = *(const uint4*)(pAl + (size_t)lr1 * K + kt + lc0);
        *(uint4*)&sBh[lr0 * SSTRIDE + lc0] = *(const uint4*)(pBh + (size_t)lr0 * K + kt + lc0);
        *(uint4*)&sBh[lr1 * SSTRIDE + lc0] = *(const uint4*)(pBh + (size_t)lr1 * K + kt + lc0);
        *(uint4*)&sBl[lr0 * SSTRIDE + lc0] = *(const uint4*)(pBl + (size_t)lr0 * K + kt + lc0);
        *(uint4*)&sBl[lr1 * SSTRIDE + lc0] = *(const uint4*)(pBl + (size_t)lr1 * K + kt + lc0);
        __syncthreads();

#pragma unroll
        for (int ks = 0; ks < 2; ++ks) {
            uint32_t fAh[4][4], fAl[4][4], fBh[2][4], fBl[2][4];
#pragma unroll
            for (int mt = 0; mt < 4; ++mt) {
                uint32_t off = (uint32_t)((wm + mt * 16 + (q & 1) * 8 + rr) * (SSTRIDE * 2)
                                          + (ks * 16 + (q >> 1) * 8) * 2);
                ldsm4(fAh[mt], aAh + off);
                ldsm4(fAl[mt], aAl + off);
            }
#pragma unroll
            for (int np = 0; np < 2; ++np) {
                uint32_t off = (uint32_t)((wn + np * 16 + (q >> 1) * 8 + rr) * (SSTRIDE * 2)
                                          + (ks * 16 + (q & 1) * 8) * 2);
                ldsm4(fBh[np], aBh + off);
                ldsm4(fBl[np], aBl + off);
            }
#pragma unroll
            for (int mt = 0; mt < 4; ++mt)
#pragma unroll
                for (int nt = 0; nt < 4; ++nt) {
                    const uint32_t* bh = &fBh[nt >> 1][(nt & 1) * 2];
                    const uint32_t* bl = &fBl[nt >> 1][(nt & 1) * 2];
                    mma16816(acc[mt][nt], fAh[mt], bh);
                    mma16816(acc[mt][nt], fAl[mt], bh);
                    mma16816(acc[mt][nt], fAh[mt], bl);
                }
        }
        __syncthreads();
    }

#pragma unroll
    for (int mt = 0; mt < 4; ++mt) {
#pragma unroll
        for (int nt = 0; nt < 4; ++nt) {
            int r = row0 + wm + mt * 16 + gr;
            int c = col0 + wn + nt * 8 + tg * 2;
            float b0 = bias[c], b1 = bias[c + 1];
            float2 v0 = make_float2(acc[mt][nt][0] + b0, acc[mt][nt][1] + b1);
            float2 v1 = make_float2(acc[mt][nt][2] + b0, acc[mt][nt][3] + b1);
            *(float2*)(C + (size_t)r * N + c) = v0;
            *(float2*)(C + (size_t)(r + 8) * N + c) = v1;
        }
    }
}

// ---------------------------------------------------------------------------
// Tensor-core flash attention.
// Block = (qtile 64, head, batch), 128 threads (4 warps, 16 q-rows each).
// KV streamed in 64-row tiles. 3-term bf16 hi/lo everywhere.
// Writes O directly as bf16 hi/lo for the O-projection.
// ---------------------------------------------------------------------------
#define QSTR 136   // bf16 elems per row (272B; 272 % 128 = 16 -> ldsm conflict-free)
#define VSTR 72    // 144B rows
#define ATT_SMEM ((4 * 64 * QSTR + 2 * 128 * VSTR) * 2)   // 106496 B

__global__ __launch_bounds__(128) void attn_tc_k(
    const __nv_bfloat16* __restrict__ Qh, const __nv_bfloat16* __restrict__ Ql,
    const __nv_bfloat16* __restrict__ Kh, const __nv_bfloat16* __restrict__ Kl,
    const __nv_bfloat16* __restrict__ Vh, const __nv_bfloat16* __restrict__ Vl,
    __nv_bfloat16* __restrict__ Oh, __nv_bfloat16* __restrict__ Ol)
{
    extern __shared__ __nv_bfloat16 smem_bf[];
    __nv_bfloat16* sQh = smem_bf;
    __nv_bfloat16* sQl = sQh + 64 * QSTR;
    __nv_bfloat16* sKh = sQl + 64 * QSTR;
    __nv_bfloat16* sKl = sKh + 64 * QSTR;
    __nv_bfloat16* sVh = sKl + 64 * QSTR;
    __nv_bfloat16* sVl = sVh + 128 * VSTR;

    const int b = blockIdx.z, head = blockIdx.y, qt = blockIdx.x;
    const int kvh = head >> 2;
    const int tid = threadIdx.x;
    const int wid = tid >> 5, lane = tid & 31;
    const int q = lane >> 3, rr = lane & 7;
    const int gr = lane >> 2, tg = lane & 3;

    const uint32_t aQh = smem_u32(sQh), aQl = smem_u32(sQl);
    const uint32_t aKh = smem_u32(sKh), aKl = smem_u32(sKl);
    const uint32_t aVh = smem_u32(sVh), aVl = smem_u32(sVl);

    // ---- load Q tile (64 x 128 bf16, hi/lo) ----
    {
        const __nv_bfloat16* qbh = Qh + (size_t)(b * L_ + qt * 64) * HID_ + head * HDIM_;
        const __nv_bfloat16* qbl = Ql + (size_t)(b * L_ + qt * 64) * HID_ + head * HDIM_;
#pragma unroll
        for (int i = 0; i < 8; i++) {
            int idx = tid + i * 128;
            int row = idx >> 4, ch = idx & 15;
            *(uint4*)&sQh[row * QSTR + ch * 8] = *(const uint4*)(qbh + (size_t)row * HID_ + ch * 8);
            *(uint4*)&sQl[row * QSTR + ch * 8] = *(const uint4*)(qbl + (size_t)row * HID_ + ch * 8);
        }
    }

    float oacc[16][4];
#pragma unroll
    for (int nt = 0; nt < 16; nt++)
#pragma unroll
        for (int e = 0; e < 4; e++) oacc[nt][e] = 0.f;
    float m0 = -1e30f, m1 = -1e30f, l0 = 0.f, l1 = 0.f;

    const __nv_bfloat16* kbh = Kh + (size_t)(b * NKV_ + kvh) * L_ * HDIM_;
    const __nv_bfloat16* kbl = Kl + (size_t)(b * NKV_ + kvh) * L_ * HDIM_;
    const __nv_bfloat16* vbh = Vh + (size_t)(b * NKV_ + kvh) * HDIM_ * L_;
    const __nv_bfloat16* vbl = Vl + (size_t)(b * NKV_ + kvh) * HDIM_ * L_;

    for (int t = 0; t < L_ / 64; ++t) {
        // ---- stage K (64x128) and Vt (128x64) tiles, hi/lo ----
#pragma unroll
        for (int i = 0; i < 8; i++) {
            int idx = tid + i * 128;
            int row = idx >> 4, ch = idx & 15;
            *(uint4*)&sKh[row * QSTR + ch * 8] =
                *(const uint4*)(kbh + (size_t)(t * 64 + row) * HDIM_ + ch * 8);
            *(uint4*)&sKl[row * QSTR + ch * 8] =
                *(const uint4*)(kbl + (size_t)(t * 64 + row) * HDIM_ + ch * 8);
            int vrow = idx >> 3, vch = idx & 7;
            *(uint4*)&sVh[vrow * VSTR + vch * 8] =
                *(const uint4*)(vbh + (size_t)vrow * L_ + t * 64 + vch * 8);
            *(uint4*)&sVl[vrow * VSTR + vch * 8] =
                *(const uint4*)(vbl + (size_t)vrow * L_ + t * 64 + vch * 8);
        }
        __syncthreads();

        // ---- S = Q K^T (16 x 64 per warp), 3-term ----
        float sacc[8][4];
#pragma unroll
        for (int nt = 0; nt < 8; nt++)
#pragma unroll
            for (int e = 0; e < 4; e++) sacc[nt][e] = 0.f;

#pragma unroll
        for (int ks = 0; ks < 8; ++ks) {
            uint32_t fQh[4], fQl[4];
            uint32_t aoff = (uint32_t)((wid * 16 + (q & 1) * 8 + rr) * (QSTR * 2)
                                       + (ks * 16 + (q >> 1) * 8) * 2);
            ldsm4(fQh, aQh + aoff);
            ldsm4(fQl, aQl + aoff);
            uint32_t fKh[4][4], fKl[4][4];
#pragma unroll
            for (int np = 0; np < 4; ++np) {
                uint32_t boff = (uint32_t)((np * 16 + (q >> 1) * 8 + rr) * (QSTR * 2)
                                           + (ks * 16 + (q & 1) * 8) * 2);
                ldsm4(fKh[np], aKh + boff);
                ldsm4(fKl[np], aKl + boff);
            }
#pragma unroll
            for (int nt = 0; nt < 8; ++nt) {
                const uint32_t* bh = &fKh[nt >> 1][(nt & 1) * 2];
                const uint32_t* bl = &fKl[nt >> 1][(nt & 1) * 2];
                mma16816(sacc[nt], fQh, bh);
                mma16816(sacc[nt], fQl, bh);
                mma16816(sacc[nt], fQh, bl);
            }
        }

        // ---- online softmax (registers + quad shuffles) ----
        float rmax0 = -1e30f, rmax1 = -1e30f;
#pragma unroll
        for (int nt = 0; nt < 8; ++nt) {
            rmax0 = fmaxf(rmax0, fmaxf(sacc[nt][0], sacc[nt][1]));
            rmax1 = fmaxf(rmax1, fmaxf(sacc[nt][2], sacc[nt][3]));
        }
        rmax0 = fmaxf(rmax0, __shfl_xor_sync(0xffffffffu, rmax0, 1));
        rmax0 = fmaxf(rmax0, __shfl_xor_sync(0xffffffffu, rmax0, 2));
        rmax1 = fmaxf(rmax1, __shfl_xor_sync(0xffffffffu, rmax1, 1));
        rmax1 = fmaxf(rmax1, __shfl_xor_sync(0xffffffffu, rmax1, 2));
        float mn0 = fmaxf(m0, rmax0), mn1 = fmaxf(m1, rmax1);
        float fact0 = __expf(m0 - mn0), fact1 = __expf(m1 - mn1);
        m0 = mn0; m1 = mn1;
        float sum0 = 0.f, sum1 = 0.f;
#pragma unroll
        for (int nt = 0; nt < 8; ++nt) {
            sacc[nt][0] = __expf(sacc[nt][0] - mn0); sum0 += sacc[nt][0];
            sacc[nt][1] = __expf(sacc[nt][1] - mn0); sum0 += sacc[nt][1];
            sacc[nt][2] = __expf(sacc[nt][2] - mn1); sum1 += sacc[nt][2];
            sacc[nt][3] = __expf(sacc[nt][3] - mn1); sum1 += sacc[nt][3];
        }
        sum0 += __shfl_xor_sync(0xffffffffu, sum0, 1);
        sum0 += __shfl_xor_sync(0xffffffffu, sum0, 2);
        sum1 += __shfl_xor_sync(0xffffffffu, sum1, 1);
        sum1 += __shfl_xor_sync(0xffffffffu, sum1, 2);
        l0 = l0 * fact0 + sum0;
        l1 = l1 * fact1 + sum1;
#pragma unroll
        for (int nt = 0; nt < 16; ++nt) {
            oacc[nt][0] *= fact0; oacc[nt][1] *= fact0;
            oacc[nt][2] *= fact1; oacc[nt][3] *= fact1;
        }

        // ---- O += P V, P fragments built in-register, 3-term ----
#pragma unroll
        for (int j = 0; j < 4; ++j) {
            uint32_t aPh[4], aPl[4];
#pragma unroll
            for (int hlf = 0; hlf < 2; ++hlf) {        // nt = 2j, 2j+1
                const float* p = sacc[2 * j + hlf];
                unsigned short h0 = f2bf_bits(p[0]), h1 = f2bf_bits(p[1]);
                unsigned short h2 = f2bf_bits(p[2]), h3 = f2bf_bits(p[3]);
                unsigned short e0 = f2bf_bits(p[0] - bf_bits2f(h0));
                unsigned short e1 = f2bf_bits(p[1] - bf_bits2f(h1));
                unsigned short e2 = f2bf_bits(p[2] - bf_bits2f(h2));
                unsigned short e3 = f2bf_bits(p[3] - bf_bits2f(h3));
                aPh[2 * hlf]     = (uint32_t)h0 | ((uint32_t)h1 << 16);
                aPh[2 * hlf + 1] = (uint32_t)h2 | ((uint32_t)h3 << 16);
                aPl[2 * hlf]     = (uint32_t)e0 | ((uint32_t)e1 << 16);
                aPl[2 * hlf + 1] = (uint32_t)e2 | ((uint32_t)e3 << 16);
            }
            // fix ordering: a-frag order is {(r,klo),(r+8,klo),(r,khi),(r+8,khi)}
            // built above as {h0h1=(r,klo),(r+8,klo)} for hlf=0 -> indices 0,1 OK;
            // hlf=1 gives khi pair -> indices 2,3 OK.
#pragma unroll
            for (int nn = 0; nn < 8; ++nn) {
                uint32_t fVh[4], fVl[4];
                uint32_t voff = (uint32_t)((nn * 16 + (q >> 1) * 8 + rr) * (VSTR * 2)
                                           + (j * 16 + (q & 1) * 8) * 2);
                ldsm4(fVh, aVh + voff);
                ldsm4(fVl, aVl + voff);
                mma16816(oacc[2 * nn], aPh, &fVh[0]);
                mma16816(oacc[2 * nn], aPl, &fVh[0]);
                mma16816(oacc[2 * nn], aPh, &fVl[0]);
                mma16816(oacc[2 * nn + 1], aPh, &fVh[2]);
                mma16816(oacc[2 * nn + 1], aPl, &fVh[2]);
                mma16816(oacc[2 * nn + 1], aPh, &fVl[2]);
            }
        }
        __syncthreads();
    }

    // ---- normalize + store O as bf16 hi/lo ----
    float inv0 = 1.0f / l0, inv1 = 1.0f / l1;
    const int row0g = b * L_ + qt * 64 + wid * 16 + gr;
    __nv_bfloat16* oh0 = Oh + (size_t)row0g * HID_ + head * HDIM_;
    __nv_bfloat16* ol0 = Ol + (size_t)row0g * HID_ + head * HDIM_;
    __nv_bfloat16* oh1 = oh0 + (size_t)8 * HID_;
    __nv_bfloat16* ol1 = ol0 + (size_t)8 * HID_;
#pragma unroll
    for (int nt = 0; nt < 16; ++nt) {
        int col = nt * 8 + tg * 2;
        float v0 = oacc[nt][0] * inv0, v1 = oacc[nt][1] * inv0;
        float v2 = oacc[nt][2] * inv1, v3 = oacc[nt][3] * inv1;
        unsigned short h0 = f2bf_bits(v0), h1 = f2bf_bits(v1);
        unsigned short h2 = f2bf_bits(v2), h3 = f2bf_bits(v3);
        unsigned short e0 = f2bf_bits(v0 - bf_bits2f(h0));
        unsigned short e1 = f2bf_bits(v1 - bf_bits2f(h1));
        unsigned short e2 = f2bf_bits(v2 - bf_bits2f(h2));
        unsigned short e3 = f2bf_bits(v3 - bf_bits2f(h3));
        *(uint32_t*)(oh0 + col) = (uint32_t)h0 | ((uint32_t)h1 << 16);
        *(uint32_t*)(ol0 + col) = (uint32_t)e0 | ((uint32_t)e1 << 16);
        *(uint32_t*)(oh1 + col) = (uint32_t)h2 | ((uint32_t)h3 << 16);
        *(uint32_t*)(ol1 + col) = (uint32_t)e2 | ((uint32_t)e3 << 16);
    }
}

// ---------------------------------------------------------------------------
extern "C" void kernel_launch(void* const* d_in, const int* in_sizes, int n_in,
                              void* d_out, int out_size)
{
    const float* query = (const float*)d_in[0];
    const float* kv    = (const float*)d_in[1];
    const float* Wq    = (const float*)d_in[2];
    const float* bq    = (const float*)d_in[3];
    const float* Wkv   = (const float*)d_in[4];
    const float* bkv   = (const float*)d_in[5];
    const float* Wo    = (const float*)d_in[6];
    const float* bo    = (const float*)d_in[7];
    float* out = (float*)d_out;

    float *pq = nullptr, *pkv = nullptr;
    cudaGetSymbolAddress((void**)&pq,  g_q);
    cudaGetSymbolAddress((void**)&pkv, g_kv);
    __nv_bfloat16 *qh, *ql, *kvh, *kvl, *ath, *atl;
    __nv_bfloat16 *wqh, *wql, *wkh, *wkl, *woh, *wol;
    __nv_bfloat16 *aqh, *aql, *akh, *akl, *avh, *avl;
    cudaGetSymbolAddress((void**)&qh,  g_qin_h);  cudaGetSymbolAddress((void**)&ql,  g_qin_l);
    cudaGetSymbolAddress((void**)&kvh, g_kvin_h); cudaGetSymbolAddress((void**)&kvl, g_kvin_l);
    cudaGetSymbolAddress((void**)&ath, g_att_h);  cudaGetSymbolAddress((void**)&atl, g_att_l);
    cudaGetSymbolAddress((void**)&wqh, g_wqt_h);  cudaGetSymbolAddress((void**)&wql, g_wqt_l);
    cudaGetSymbolAddress((void**)&wkh, g_wkvt_h); cudaGetSymbolAddress((void**)&wkl, g_wkvt_l);
    cudaGetSymbolAddress((void**)&woh, g_wot_h);  cudaGetSymbolAddress((void**)&wol, g_wot_l);
    cudaGetSymbolAddress((void**)&aqh, g_aqh);    cudaGetSymbolAddress((void**)&aql, g_aql);
    cudaGetSymbolAddress((void**)&akh, g_kh);     cudaGetSymbolAddress((void**)&akl, g_kl);
    cudaGetSymbolAddress((void**)&avh, g_vth);    cudaGetSymbolAddress((void**)&avl, g_vtl);

    cudaFuncSetAttribute(attn_tc_k, cudaFuncAttributeMaxDynamicSharedMemorySize,
                         ATT_SMEM);

    const int n_act4 = (MROWS * HID_) / 4;
    const float qscale = 0.08838834764831845f;   // 1/sqrt(128)

    // 1) split input activations
    split_k<<<(n_act4 + 255) / 256, 256>>>(query, qh, ql, n_act4, 1.0f);
    split_k<<<(n_act4 + 255) / 256, 256>>>(kv, kvh, kvl, n_act4, 1.0f);
    // 2) transpose+split weights
    tsplit_k<<<dim3(HID_ / 32, HID_ / 32), dim3(32, 8)>>>(Wq,  wqh, wql, HID_, HID_);
    tsplit_k<<<dim3(KVW  / 32, HID_ / 32), dim3(32, 8)>>>(Wkv, wkh, wkl, HID_, KVW);
    tsplit_k<<<dim3(HID_ / 32, HID_ / 32), dim3(32, 8)>>>(Wo,  woh, wol, HID_, HID_);
    // 3) projections on tensor cores
    hgemm_k<<<dim3(HID_ / 128, MROWS / 128), 256>>>(qh, ql, wqh, wql, bq, pq,
                                                    MROWS, HID_, HID_);
    hgemm_k<<<dim3(KVW / 128, MROWS / 128), 256>>>(kvh, kvl, wkh, wkl, bkv, pkv,
                                                   MROWS, KVW, HID_);
    // 4) attention operand prep (scaled Q split; K rearrange; V transpose)
    split_k<<<(n_act4 + 255) / 256, 256>>>(pq, aqh, aql, n_act4, qscale);
    kprep_k<<<(B_ * NKV_ * L_ * (HDIM_ / 4) + 255) / 256, 256>>>(pkv, akh, akl);
    vtprep_k<<<dim3(L_ / 32, HDIM_ / 32, B_ * NKV_), dim3(32, 8)>>>(pkv, avh, avl);
    // 5) tensor-core attention -> bf16 hi/lo O
    attn_tc_k<<<dim3(L_ / 64, NHEAD_, B_), 128, ATT_SMEM>>>(
        aqh, aql, akh, akl, avh, avl, ath, atl);
    // 6) O projection
    hgemm_k<<<dim3(HID_ / 128, MROWS / 128), 256>>>(ath, atl, woh, wol, bo, out,
                                                    MROWS, HID_, HID_);
}